// round 15
// baseline (speedup 1.0000x reference)
#include <cuda_runtime.h>

#define RR 4
#define ND 81
#define HH 128
#define WW 256
#define CC 128
#define BB 8
#define HW (HH*WW)

#define HT 8                 // tile height
#define WT 16                // tile width
#define PW 4                 // pixels per thread (w)
#define CB 8                 // channels per stage
#define NCHUNK (CC/CB)       // 16 global chunks (8 per consumer set)
#define NSTG 4               // ring: set A owns stages {0,2}, set B owns {1,3}
#define WROWS (HT + 2*RR)    // 16
#define WROW 28              // warped row stride (floats); 24 used
#define XROW 20              // x row stride (floats); 16 used
#define WCH (WROWS*WROW)     // 448
#define XCH (HT*XROW)        // 160
#define CHSZ (WCH + XCH)     // 608 floats / channel
#define STG (CB*CHSZ)        // 4864 floats / stage
#define MBAR_OFF (NSTG*STG*4)           // 77824
#define SMEM_BYTES (MBAR_OFF + 64)
#define NCONS 288            // consumer threads per set
#define NTHR (2*NCONS + 32)  // 608: set A + set B + producer warp
#define NITEM 4              // staging items per producer lane (128 total)

typedef unsigned long long u64t;

static __device__ __forceinline__ u64t pk2(float lo, float hi) {
    return __double_as_longlong(__hiloint2double(__float_as_int(hi), __float_as_int(lo)));
}
static __device__ __forceinline__ void fma2(u64t &acc, u64t a, u64t b) {
    asm("fma.rn.f32x2 %0, %1, %2, %0;" : "+l"(acc) : "l"(a), "l"(b));
}
static __device__ __forceinline__ float lo32(u64t v) {
    return __int_as_float(__double2loint(__longlong_as_double(v)));
}
static __device__ __forceinline__ float hi32(u64t v) {
    return __int_as_float(__double2hiint(__longlong_as_double(v)));
}
static __device__ __forceinline__ void cpa16(unsigned dst, const float* src) {
    asm volatile("cp.async.cg.shared.global [%0], [%1], 16;" :: "r"(dst), "l"(src));
}
static __device__ __forceinline__ void mb_init(unsigned a, unsigned cnt) {
    asm volatile("mbarrier.init.shared.b64 [%0], %1;" :: "r"(a), "r"(cnt) : "memory");
}
static __device__ __forceinline__ void mb_arrive(unsigned a) {
    asm volatile("mbarrier.arrive.release.cta.shared::cta.b64 _, [%0];" :: "r"(a) : "memory");
}
static __device__ __forceinline__ void mb_wait(unsigned a, unsigned parity) {
    asm volatile(
        "{\n\t.reg .pred P1;\n\t"
        "WL_%=:\n\t"
        "mbarrier.try_wait.parity.acquire.cta.shared::cta.b64 P1, [%0], %1, 0x989680;\n\t"
        "@P1 bra.uni WD_%=;\n\t"
        "bra.uni WL_%=;\n\t"
        "WD_%=:\n\t}"
        :: "r"(a), "r"(parity) : "memory");
}

extern __shared__ __align__(16) float smf[];

__global__ void __launch_bounds__(NTHR, 2)
cost_volume_kernel(const float* __restrict__ gx, const float* __restrict__ gw,
                   float* __restrict__ gout)
{
    const int tid = threadIdx.x;
    const int w0  = blockIdx.x * WT;
    const int h0  = blockIdx.y * HT;
    const int b   = blockIdx.z;

    const float* xb = gx + (size_t)b * CC * HW;
    const float* wb = gw + (size_t)b * CC * HW;
    const unsigned smb = (unsigned)__cvta_generic_to_shared(smf);
    const unsigned mbF0 = smb + MBAR_OFF;   // full[s] at +s*16, empty[s] at +s*16+8

    if (tid == 0) {
        #pragma unroll
        for (int s = 0; s < NSTG; s++) {
            mb_init(mbF0 + s * 16, 32);      // full: 32 producer lanes
            mb_init(mbF0 + s * 16 + 8, 9);   // empty: 9 warp-elects of the owning set
        }
    }
    // OOB warped slots are channel-independent: zero once in every ring stage
    if (tid < 96) {
        const int row = tid / 6, q = tid % 6;
        const int gh   = h0 - RR + row;
        const int gcol = w0 - RR + q * 4;
        if (!(((unsigned)gh < HH) && (gcol >= 0) && (gcol + 4 <= WW))) {
            const int so = row * WROW + q * 4;
            for (int s = 0; s < NSTG; s++)
                for (int cc2 = 0; cc2 < CB; cc2++)
                    *(float4*)(smf + s * STG + cc2 * CHSZ + so) =
                        make_float4(0.f, 0.f, 0.f, 0.f);
        }
    }
    __syncthreads();

    // per-consumer accumulators survive to the reduction epilogue
    u64t acc[18];
    #pragma unroll
    for (int i = 0; i < 18; i++) acc[i] = 0ULL;

    const int setid = (tid < NCONS) ? 0 : ((tid < 2 * NCONS) ? 1 : 2);

    if (setid == 2) {
        // ================= producer warp =================
        const int lane = tid - 2 * NCONS;
        const float* src[NITEM]; unsigned doff[NITEM]; bool val[NITEM];
        #pragma unroll
        for (int k = 0; k < NITEM; k++) {
            const int it = lane + 32 * k;
            if (it < 96) {                       // warped halo: 16 rows x 6 quads
                const int row = it / 6, q = it % 6;
                const int gh   = h0 - RR + row;
                const int gcol = w0 - RR + q * 4;
                doff[k] = (unsigned)((row * WROW + q * 4) * 4);
                val[k]  = ((unsigned)gh < HH) && (gcol >= 0) && (gcol + 4 <= WW);
                src[k]  = val[k] ? (wb + (size_t)gh * WW + gcol) : wb;
            } else {                             // x tile: 8 rows x 4 quads
                const int i = it - 96;
                const int row = i / 4, q = i % 4;
                doff[k] = (unsigned)((WCH + row * XROW + q * 4) * 4);
                src[k]  = xb + (size_t)(h0 + row) * WW + w0 + q * 4;
                val[k]  = true;
            }
        }

        int es = 0, eph = 0;
        int ps = 0, prev = 0;
        #pragma unroll 1
        for (int chunk = 0; chunk < NCHUNK; chunk++) {
            if (chunk >= NSTG) {
                mb_wait(mbF0 + es * 16 + 8, (unsigned)eph);
                if (++es == NSTG) { es = 0; eph ^= 1; }
            }
            const unsigned sb = smb + (unsigned)(ps * STG * 4);
            #pragma unroll
            for (int cc = 0; cc < CB; cc++) {
                #pragma unroll
                for (int k = 0; k < NITEM; k++)
                    if (val[k]) cpa16(sb + doff[k] + (unsigned)(cc * CHSZ * 4),
                                      src[k] + cc * HW);
            }
            #pragma unroll
            for (int k = 0; k < NITEM; k++) src[k] += CB * HW;
            asm volatile("cp.async.commit_group;" ::: "memory");
            if (chunk >= 1) {
                asm volatile("cp.async.wait_group 1;" ::: "memory");
                mb_arrive(mbF0 + prev * 16);
            }
            prev = ps;
            if (++ps == NSTG) ps = 0;
        }
        asm volatile("cp.async.wait_group 0;" ::: "memory");
        mb_arrive(mbF0 + prev * 16);
    } else {
        // ================= consumer warps (set A: even chunks, set B: odd) =================
        const int cid = tid - setid * NCONS;    // 0..287
        const int dig = cid % 9;
        const int hwg = cid / 9;
        const int h_i = hwg & 7;
        const int wg  = hwg >> 3;

        const int woff = (h_i + dig) * WROW + wg * PW;
        const int xoff = WCH + h_i * XROW + wg * PW;

        int st = setid;                         // A: 0,2,0,2...  B: 1,3,1,3...
        int ph = 0;
        #pragma unroll 1
        for (int oc = 0; oc < NCHUNK / 2; oc++) {
            mb_wait(mbF0 + st * 16, (unsigned)ph);

            const float* sb = smf + st * STG;
            #pragma unroll
            for (int cc2 = 0; cc2 < CB; cc2++) {
                const float* base = sb + cc2 * CHSZ;
                const float4* wv4 = (const float4*)(base + woff);

                float4 q0 = wv4[0], q1 = wv4[1], q2 = wv4[2];
                float4 xq = *(const float4*)(base + xoff);

                u64t pr[11];
                pr[0]  = pk2(q0.x, q0.y);
                pr[1]  = pk2(q0.y, q0.z);
                pr[2]  = pk2(q0.z, q0.w);
                pr[3]  = pk2(q0.w, q1.x);
                pr[4]  = pk2(q1.x, q1.y);
                pr[5]  = pk2(q1.y, q1.z);
                pr[6]  = pk2(q1.z, q1.w);
                pr[7]  = pk2(q1.w, q2.x);
                pr[8]  = pk2(q2.x, q2.y);
                pr[9]  = pk2(q2.y, q2.z);
                pr[10] = pk2(q2.z, q2.w);

                u64t xv[2] = { pk2(xq.x, xq.y), pk2(xq.z, xq.w) };

                #pragma unroll
                for (int p = 0; p < 2; p++) {
                    #pragma unroll
                    for (int dj = 0; dj < 9; dj++) {
                        fma2(acc[dj * 2 + p], xv[p], pr[dj + 2 * p]);
                    }
                }
            }

            if ((cid & 31) == 0) mb_arrive(mbF0 + st * 16 + 8);
            st ^= 2;                            // toggle within the set's sub-ring
            if (oc & 1) ph ^= 1;                // parity flips after both stages used
        }
    }

    // ================= cross-set reduction + store =================
    __syncthreads();                            // pipeline fully drained; smem reusable

    u64t* red = (u64t*)smf;                     // 288*18*8B = 41472B < stage area
    if (setid == 1) {
        const int cid = tid - NCONS;
        #pragma unroll
        for (int i = 0; i < 18; i++) red[cid * 18 + i] = acc[i];
    }
    __syncthreads();

    if (setid == 0) {
        const int cid = tid;
        const int dig = cid % 9;
        const int hwg = cid / 9;
        const int h_i = hwg & 7;
        const int wg  = hwg >> 3;

        const float sc = 1.0f / (float)(CC * ND);
        float* ob = gout + (((size_t)b * ND + dig * 9) * HH + (h0 + h_i)) * WW + w0 + wg * PW;
        #pragma unroll
        for (int dj = 0; dj < 9; dj++) {
            float* od = ob + (size_t)dj * HW;
            #pragma unroll
            for (int p = 0; p < 2; p++) {
                const u64t va = acc[dj * 2 + p];
                const u64t vb = red[cid * 18 + dj * 2 + p];
                float2 r2;
                r2.x = (lo32(va) + lo32(vb)) * sc;
                r2.y = (hi32(va) + hi32(vb)) * sc;
                *(float2*)(od + 2 * p) = r2;
            }
        }
    }
}

extern "C" void kernel_launch(void* const* d_in, const int* in_sizes, int n_in,
                              void* d_out, int out_size) {
    const float* x = (const float*)d_in[0];
    const float* w = (const float*)d_in[1];
    float* out = (float*)d_out;
    cudaFuncSetAttribute(cost_volume_kernel,
                         cudaFuncAttributeMaxDynamicSharedMemorySize, SMEM_BYTES);
    dim3 grid(WW / WT, HH / HT, BB);   // (16, 16, 8) = 2048 blocks
    cost_volume_kernel<<<grid, NTHR, SMEM_BYTES>>>(x, w, out);
}

// round 16
// speedup vs baseline: 2.3671x; 2.3671x over previous
#include <cuda_runtime.h>

#define RR 4
#define ND 81
#define HH 128
#define WW 256
#define CC 128
#define BB 8
#define HW (HH*WW)

#define HT 8                 // tile height
#define WT 16                // tile width
#define PW 4                 // pixels per thread (w)
#define CB 8                 // channels per stage
#define NCHUNK (CC/CB)       // 16
#define NSTG 4               // pipeline ring
#define WROWS (HT + 2*RR)    // 16
#define WROW 28              // warped row stride (floats); 24 used
#define XROW 20              // x row stride (floats); 16 used
#define WCH (WROWS*WROW)     // 448
#define XCH (HT*XROW)        // 160
#define CHSZ (WCH + XCH)     // 608 floats / channel
#define STG (CB*CHSZ)        // 4864 floats / stage
#define MBAR_OFF (NSTG*STG*4)           // 77824
#define SMEM_BYTES (MBAR_OFF + 64)
#define NTHR 320             // 9 consumer warps + 1 producer warp
#define NITEM 4              // staging items per producer lane (128 total)

typedef unsigned long long u64t;

static __device__ __forceinline__ u64t pk2(float lo, float hi) {
    return __double_as_longlong(__hiloint2double(__float_as_int(hi), __float_as_int(lo)));
}
static __device__ __forceinline__ void fma2(u64t &acc, u64t a, u64t b) {
    asm("fma.rn.f32x2 %0, %1, %2, %0;" : "+l"(acc) : "l"(a), "l"(b));
}
static __device__ __forceinline__ float lo32(u64t v) {
    return __int_as_float(__double2loint(__longlong_as_double(v)));
}
static __device__ __forceinline__ float hi32(u64t v) {
    return __int_as_float(__double2hiint(__longlong_as_double(v)));
}
static __device__ __forceinline__ void cpa16(unsigned dst, const float* src) {
    asm volatile("cp.async.cg.shared.global [%0], [%1], 16;" :: "r"(dst), "l"(src));
}
static __device__ __forceinline__ void mb_init(unsigned a, unsigned cnt) {
    asm volatile("mbarrier.init.shared.b64 [%0], %1;" :: "r"(a), "r"(cnt) : "memory");
}
static __device__ __forceinline__ void mb_arrive(unsigned a) {
    asm volatile("mbarrier.arrive.release.cta.shared::cta.b64 _, [%0];" :: "r"(a) : "memory");
}
static __device__ __forceinline__ void mb_wait(unsigned a, unsigned parity) {
    asm volatile(
        "{\n\t.reg .pred P1;\n\t"
        "WL_%=:\n\t"
        "mbarrier.try_wait.parity.acquire.cta.shared::cta.b64 P1, [%0], %1, 0x989680;\n\t"
        "@P1 bra.uni WD_%=;\n\t"
        "bra.uni WL_%=;\n\t"
        "WD_%=:\n\t}"
        :: "r"(a), "r"(parity) : "memory");
}

extern __shared__ __align__(16) float smf[];

__global__ void __launch_bounds__(NTHR, 2)
cost_volume_kernel(const float* __restrict__ gx, const float* __restrict__ gw,
                   float* __restrict__ gout)
{
    const int tid = threadIdx.x;
    const int w0  = blockIdx.x * WT;
    const int h0  = blockIdx.y * HT;
    const int b   = blockIdx.z;

    const float* xb = gx + (size_t)b * CC * HW;
    const float* wb = gw + (size_t)b * CC * HW;
    const unsigned smb = (unsigned)__cvta_generic_to_shared(smf);
    const unsigned mbF0 = smb + MBAR_OFF;   // full[s] at +s*16, empty[s] at +s*16+8

    if (tid == 0) {
        #pragma unroll
        for (int s = 0; s < NSTG; s++) {
            mb_init(mbF0 + s * 16, 32);      // full: 32 producer lanes
            mb_init(mbF0 + s * 16 + 8, 9);   // empty: 9 consumer warp-elects
        }
    }
    // OOB warped slots are channel-independent: zero once in every ring stage
    if (tid < 96) {
        const int row = tid / 6, q = tid % 6;
        const int gh   = h0 - RR + row;
        const int gcol = w0 - RR + q * 4;
        if (!(((unsigned)gh < HH) && (gcol >= 0) && (gcol + 4 <= WW))) {
            const int so = row * WROW + q * 4;
            for (int s = 0; s < NSTG; s++)
                for (int cc2 = 0; cc2 < CB; cc2++)
                    *(float4*)(smf + s * STG + cc2 * CHSZ + so) =
                        make_float4(0.f, 0.f, 0.f, 0.f);
        }
    }
    __syncthreads();

    if (tid >= 288) {
        // ================= producer warp =================
        const int lane = tid - 288;
        const float* src[NITEM]; unsigned doff[NITEM]; bool val[NITEM];
        #pragma unroll
        for (int k = 0; k < NITEM; k++) {
            const int it = lane + 32 * k;
            if (it < 96) {                       // warped halo: 16 rows x 6 quads
                const int row = it / 6, q = it % 6;
                const int gh   = h0 - RR + row;
                const int gcol = w0 - RR + q * 4;
                doff[k] = (unsigned)((row * WROW + q * 4) * 4);
                val[k]  = ((unsigned)gh < HH) && (gcol >= 0) && (gcol + 4 <= WW);
                src[k]  = val[k] ? (wb + (size_t)gh * WW + gcol) : wb;
            } else {                             // x tile: 8 rows x 4 quads
                const int i = it - 96;
                const int row = i / 4, q = i % 4;
                doff[k] = (unsigned)((WCH + row * XROW + q * 4) * 4);
                src[k]  = xb + (size_t)(h0 + row) * WW + w0 + q * 4;
                val[k]  = true;
            }
        }

        int es = 0, eph = 0;
        int ps = 0, prev = 0;
        #pragma unroll 1
        for (int chunk = 0; chunk < NCHUNK; chunk++) {
            if (chunk >= NSTG) {
                mb_wait(mbF0 + es * 16 + 8, (unsigned)eph);
                if (++es == NSTG) { es = 0; eph ^= 1; }
            }
            const unsigned sb = smb + (unsigned)(ps * STG * 4);
            #pragma unroll
            for (int cc = 0; cc < CB; cc++) {
                #pragma unroll
                for (int k = 0; k < NITEM; k++)
                    if (val[k]) cpa16(sb + doff[k] + (unsigned)(cc * CHSZ * 4),
                                      src[k] + cc * HW);
            }
            #pragma unroll
            for (int k = 0; k < NITEM; k++) src[k] += CB * HW;
            asm volatile("cp.async.commit_group;" ::: "memory");
            if (chunk >= 1) {
                asm volatile("cp.async.wait_group 1;" ::: "memory");
                mb_arrive(mbF0 + prev * 16);
            }
            prev = ps;
            if (++ps == NSTG) ps = 0;
        }
        asm volatile("cp.async.wait_group 0;" ::: "memory");
        mb_arrive(mbF0 + prev * 16);
    } else {
        // ================= consumer warps =================
        const int dig = tid % 9;        // di + 4
        const int hwg = tid / 9;        // 0..31
        const int h_i = hwg & 7;
        const int wg  = hwg >> 3;       // 0..3

        const int woff = (h_i + dig) * WROW + wg * PW;   // 16B aligned
        const int xoff = WCH + h_i * XROW + wg * PW;     // 16B aligned

        u64t acc[18];                   // [dj(9)][pixel-pair(2)]
        #pragma unroll
        for (int i = 0; i < 18; i++) acc[i] = 0ULL;

        int st = 0, ph = 0;
        #pragma unroll 1
        for (int chunk = 0; chunk < NCHUNK; chunk++) {
            mb_wait(mbF0 + st * 16, (unsigned)ph);

            const float* sb = smf + st * STG;

            // explicit cur/next register double-buffer across channels:
            // issue channel cc2+1's loads before channel cc2's FMAs so the
            // LDS latency overlaps compute (regs permit at 2 blocks/SM).
            float4 q0, q1, q2, xq;
            q0 = *(const float4*)(sb + woff);
            q1 = *(const float4*)(sb + woff + 4);
            q2 = *(const float4*)(sb + woff + 8);
            xq = *(const float4*)(sb + xoff);

            #pragma unroll
            for (int cc2 = 0; cc2 < CB; cc2++) {
                float4 n0, n1, n2, nx;
                if (cc2 + 1 < CB) {
                    const float* bn = sb + (cc2 + 1) * CHSZ;
                    n0 = *(const float4*)(bn + woff);
                    n1 = *(const float4*)(bn + woff + 4);
                    n2 = *(const float4*)(bn + woff + 8);
                    nx = *(const float4*)(bn + xoff);
                }

                u64t pr[11];
                pr[0]  = pk2(q0.x, q0.y);
                pr[1]  = pk2(q0.y, q0.z);
                pr[2]  = pk2(q0.z, q0.w);
                pr[3]  = pk2(q0.w, q1.x);
                pr[4]  = pk2(q1.x, q1.y);
                pr[5]  = pk2(q1.y, q1.z);
                pr[6]  = pk2(q1.z, q1.w);
                pr[7]  = pk2(q1.w, q2.x);
                pr[8]  = pk2(q2.x, q2.y);
                pr[9]  = pk2(q2.y, q2.z);
                pr[10] = pk2(q2.z, q2.w);

                u64t xv0 = pk2(xq.x, xq.y);
                u64t xv1 = pk2(xq.z, xq.w);

                #pragma unroll
                for (int dj = 0; dj < 9; dj++) {
                    fma2(acc[dj * 2 + 0], xv0, pr[dj]);
                    fma2(acc[dj * 2 + 1], xv1, pr[dj + 2]);
                }

                if (cc2 + 1 < CB) { q0 = n0; q1 = n1; q2 = n2; xq = nx; }
            }

            if ((tid & 31) == 0) mb_arrive(mbF0 + st * 16 + 8);
            if (++st == NSTG) { st = 0; ph ^= 1; }
        }

        // epilogue: scale by 1/(C*81), write 9 dj planes x 4 pixels
        const float sc = 1.0f / (float)(CC * ND);
        float* ob = gout + (((size_t)b * ND + dig * 9) * HH + (h0 + h_i)) * WW + w0 + wg * PW;
        #pragma unroll
        for (int dj = 0; dj < 9; dj++) {
            float* od = ob + (size_t)dj * HW;
            #pragma unroll
            for (int p = 0; p < 2; p++) {
                u64t v = acc[dj * 2 + p];
                float2 r2;
                r2.x = lo32(v) * sc;
                r2.y = hi32(v) * sc;
                *(float2*)(od + 2 * p) = r2;
            }
        }
    }
}

extern "C" void kernel_launch(void* const* d_in, const int* in_sizes, int n_in,
                              void* d_out, int out_size) {
    const float* x = (const float*)d_in[0];
    const float* w = (const float*)d_in[1];
    float* out = (float*)d_out;
    cudaFuncSetAttribute(cost_volume_kernel,
                         cudaFuncAttributeMaxDynamicSharedMemorySize, SMEM_BYTES);
    dim3 grid(WW / WT, HH / HT, BB);   // (16, 16, 8) = 2048 blocks
    cost_volume_kernel<<<grid, NTHR, SMEM_BYTES>>>(x, w, out);
}